// round 5
// baseline (speedup 1.0000x reference)
#include <cuda_runtime.h>
#include <cstdint>

// ---------------------------------------------------------------------------
// Sequential LSTM rollout, N=10000 steps, H=1024.
// 128 persistent CTAs x 256 threads, W_hh in registers (f32x2 pairs).
// Publish protocol = R1's PROVEN strong chain per CTA:
//   lanes<8 st.cg h -> __syncwarp -> lane0 __threadfence -> lane0 st.release flag
// Consumer = per-warp: lanes 0-15 ld.acquire the 16 producer-CTA flags of this
// warp's k-slice, lane 16 ld.acquire the OWN-CTA flag (bounds run-ahead to one
// step), then __ldcg the slice into warp-private smem, __syncwarp.
// Exactly ONE __syncthreads per step (sh_part handoff); sh_part is
// parity-double-buffered, overwrite-safe under the 1-step skew bound.
// Buffers (h and flags) double-buffered by step parity.
// CTA b owns h[8b..8b+8) and gate rows {g*1024 + 8b + j}.
// Warp w owns k in [128w,128w+128).
// ---------------------------------------------------------------------------

#define HDIM  1024
#define NCTA  128
#define TPB   256
#define NWARP 8
#define WPT   64           // f32x2 weight pairs per thread (=128 k floats)

typedef unsigned long long ull;

__device__ __align__(16) float    g_hbuf[2][HDIM];
__device__ unsigned               g_flag[2][NCTA];

__device__ __forceinline__ ull ffma2(ull a, ull b, ull c) {
    ull d;
    asm("fma.rn.f32x2 %0, %1, %2, %3;" : "=l"(d) : "l"(a), "l"(b), "l"(c));
    return d;
}
__device__ __forceinline__ ull fadd2(ull a, ull b) {
    ull d;
    asm("add.rn.f32x2 %0, %1, %2;" : "=l"(d) : "l"(a), "l"(b));
    return d;
}
__device__ __forceinline__ float pairsum(ull a) {
    float lo = __uint_as_float((unsigned)(a & 0xffffffffull));
    float hi = __uint_as_float((unsigned)(a >> 32));
    return lo + hi;
}
__device__ __forceinline__ float sigf(float x) {
    return 1.0f / (1.0f + __expf(-x));
}
__device__ __forceinline__ unsigned ld_acq(const unsigned* p) {
    unsigned v;
    asm volatile("ld.acquire.gpu.u32 %0, [%1];" : "=r"(v) : "l"(p));
    return v;
}

__global__ void __launch_bounds__(TPB) lstm_init_kernel() {
    int t = threadIdx.x;
    if (t < NCTA) { g_flag[0][t] = 0u; g_flag[1][t] = 0u; }
}

__global__ void __launch_bounds__(TPB) lstm_kernel(
    const float* __restrict__ x,      // [1024]
    const float* __restrict__ W_ih,   // [4096,1024] row-major
    const float* __restrict__ W_hh,   // [4096,1024] row-major
    const float* __restrict__ b_ih,   // [4096]
    const float* __restrict__ b_hh,   // [4096]
    float* __restrict__ out,          // [N,1024]
    int N)
{
    __shared__ float sh_h[HDIM];            // warp w owns [128w,128w+128): private
    __shared__ float sh_part[2][TPB];       // parity-double-buffered partials

    const int tid = threadIdx.x;
    const int w   = tid >> 5;
    const int l   = tid & 31;
    const int cta = blockIdx.x;
    const int gt  = l >> 3;                  // gate 0..3 (i,f,g,o)
    const int jj  = l & 7;                   // local h index 0..7
    const int rowG = gt * HDIM + cta * 8 + jj;

    // ---- stage x into shared (reuse sh_h) ----
    ((float4*)sh_h)[tid] = ((const float4*)x)[tid];
    __syncthreads();

    // ---- prologue: x_gates = x @ W_ih^T + b_ih + b_hh for this CTA's rows ----
    float xgi = 0.f, xgf = 0.f, xgg = 0.f, xgo = 0.f;
    {
        const ull* wp = (const ull*)W_ih + (size_t)rowG * (HDIM / 2) + w * WPT;
        const ull* hp = (const ull*)sh_h + w * WPT;
        ull a0 = 0, a1 = 0, a2 = 0, a3 = 0;
        #pragma unroll
        for (int i = 0; i < WPT; i += 4) {
            a0 = ffma2(wp[i + 0], hp[i + 0], a0);
            a1 = ffma2(wp[i + 1], hp[i + 1], a1);
            a2 = ffma2(wp[i + 2], hp[i + 2], a2);
            a3 = ffma2(wp[i + 3], hp[i + 3], a3);
        }
        a0 = fadd2(a0, a1); a2 = fadd2(a2, a3); a0 = fadd2(a0, a2);
        sh_part[0][w * 32 + l] = pairsum(a0);
        __syncthreads();
        if (w == 0) {
            float s = 0.f;
            #pragma unroll
            for (int ww = 0; ww < NWARP; ww++) s += sh_part[0][ww * 32 + l];
            s += b_ih[rowG] + b_hh[rowG];
            float s_f = __shfl_sync(0xffffffffu, s, l + 8);
            float s_g = __shfl_sync(0xffffffffu, s, l + 16);
            float s_o = __shfl_sync(0xffffffffu, s, l + 24);
            if (l < 8) { xgi = s; xgf = s_f; xgg = s_g; xgo = s_o; }
        }
        __syncthreads();
    }

    // ---- preload W_hh slice into registers ----
    ull wreg[WPT];
    {
        const ull* wp = (const ull*)W_hh + (size_t)rowG * (HDIM / 2) + w * WPT;
        #pragma unroll
        for (int i = 0; i < WPT; i++) wreg[i] = wp[i];
    }

    // flag address this lane polls (lanes 0-15: slice CTAs; lane 16: own CTA)
    const int pollIdx = (l < 16) ? (w * 16 + l) : cta;
    const bool doPoll = (l <= 16);

    // ---- recurrence: ONE __syncthreads per step ----
    float c = 0.f;

    for (int t = 0; t < N; ++t) {
        float dot = 0.f;
        if (t > 0) {
            const int p = (t - 1) & 1;
            const unsigned tt = (unsigned)t;
            const unsigned* fp = &g_flag[p][pollIdx];
            // per-warp acquire poll: 16 slice flags + own flag (run-ahead bound)
            bool ok;
            do {
                ok = doPoll ? (ld_acq(fp) >= tt) : true;
            } while (!__all_sync(0xffffffffu, ok));

            // stage this warp's k-slice into its private smem region
            float4 hv = __ldcg((const float4*)(g_hbuf[p] + w * 128) + l);
            *((float4*)(sh_h + w * 128) + l) = hv;
            __syncwarp();

            const ull* hp = (const ull*)(sh_h + w * 128);
            ull c0 = 0, c1 = 0, c2 = 0, c3 = 0;
            #pragma unroll
            for (int i = 0; i < WPT; i += 4) {
                c0 = ffma2(wreg[i + 0], hp[i + 0], c0);
                c1 = ffma2(wreg[i + 1], hp[i + 1], c1);
                c2 = ffma2(wreg[i + 2], hp[i + 2], c2);
                c3 = ffma2(wreg[i + 3], hp[i + 3], c3);
            }
            c0 = fadd2(c0, c1); c2 = fadd2(c2, c3); c0 = fadd2(c0, c2);
            dot = pairsum(c0);
        }
        sh_part[t & 1][w * 32 + l] = dot;
        __syncthreads();

        if (w == 0) {
            float s = 0.f;
            #pragma unroll
            for (int ww = 0; ww < NWARP; ww++) s += sh_part[t & 1][ww * 32 + l];
            float s_f = __shfl_sync(0xffffffffu, s, l + 8);
            float s_g = __shfl_sync(0xffffffffu, s, l + 16);
            float s_o = __shfl_sync(0xffffffffu, s, l + 24);
            if (l < 8) {
                float iv = sigf(xgi + s);
                float fv = sigf(xgf + s_f);
                float gv = tanhf(xgg + s_g);
                float ov = sigf(xgo + s_o);
                c = fv * c + iv * gv;
                float hn = ov * tanhf(c);
                __stcg(&g_hbuf[t & 1][cta * 8 + l], hn);
                __stcs(out + (size_t)t * HDIM + cta * 8 + l, hn);
            }
            __syncwarp();
            if (l == 0) {
                __threadfence();
                asm volatile("st.release.gpu.u32 [%0], %1;"
                             :: "l"(&g_flag[t & 1][cta]), "r"((unsigned)(t + 1))
                             : "memory");
            }
        }
        // no trailing barrier: sh_part for step t+1 has opposite parity, and a
        // non-0 warp reaches step t+2's write of sh_part[t&1] only after own
        // warp 0 released flag t+2 (end of step t+1), i.e. after warp 0's
        // step-t reads of sh_part[t&1] completed.
    }
}

extern "C" void kernel_launch(void* const* d_in, const int* in_sizes, int n_in,
                              void* d_out, int out_size) {
    const float* x    = (const float*)d_in[0];
    const float* W_ih = (const float*)d_in[1];
    const float* W_hh = (const float*)d_in[2];
    const float* b_ih = (const float*)d_in[3];
    const float* b_hh = (const float*)d_in[4];
    float* out = (float*)d_out;
    const int N = out_size / HDIM;

    lstm_init_kernel<<<1, TPB>>>();
    lstm_kernel<<<NCTA, TPB>>>(x, W_ih, W_hh, b_ih, b_hh, out, N);
}

// round 7
// speedup vs baseline: 5.1099x; 5.1099x over previous
#include <cuda_runtime.h>
#include <cstdint>

// ---------------------------------------------------------------------------
// Sequential LSTM rollout, N=10000 steps, H=1024.
// 128 persistent CTAs x 256 threads, W_hh in registers (f32x2 pairs).
// Publish: lanes<8 st.cg h -> __syncwarp -> lane0 __threadfence ->
//          red.global.add g_cnt,1  (aggregate counter, no per-CTA flags)
// Observe: ONE lane per CTA polls ld.acquire.gpu g_cnt >= 128*t, then relays
//          through shared memory (st.release.cta / ld.acquire.cta spin) ->
//          zero L2 poll contention. Output store moved AFTER the release so
//          the threadfence never drains the DRAM-bound out write.
// Counter requires ALL CTAs -> run-ahead bounded to 1 step -> parity
// double-buffered g_hbuf / sh_part are overwrite-safe with ONE
// __syncthreads per step.
// CTA b owns h[8b..8b+8) and gate rows {g*1024 + 8b + j}.
// Warp w owns k in [128w,128w+128).
// ---------------------------------------------------------------------------

#define HDIM  1024
#define NCTA  128
#define TPB   256
#define NWARP 8
#define WPT   64           // f32x2 weight pairs per thread (=128 k floats)

typedef unsigned long long ull;

__device__ __align__(16) float g_hbuf[2][HDIM];
__device__ unsigned            g_cnt;

__device__ __forceinline__ ull ffma2(ull a, ull b, ull c) {
    ull d;
    asm("fma.rn.f32x2 %0, %1, %2, %3;" : "=l"(d) : "l"(a), "l"(b), "l"(c));
    return d;
}
__device__ __forceinline__ ull fadd2(ull a, ull b) {
    ull d;
    asm("add.rn.f32x2 %0, %1, %2;" : "=l"(d) : "l"(a), "l"(b));
    return d;
}
__device__ __forceinline__ float pairsum(ull a) {
    float lo = __uint_as_float((unsigned)(a & 0xffffffffull));
    float hi = __uint_as_float((unsigned)(a >> 32));
    return lo + hi;
}
__device__ __forceinline__ float sigf(float x) {
    return 1.0f / (1.0f + __expf(-x));
}
__device__ __forceinline__ unsigned ld_acq_gpu(const unsigned* p) {
    unsigned v;
    asm volatile("ld.acquire.gpu.u32 %0, [%1];" : "=r"(v) : "l"(p));
    return v;
}
__device__ __forceinline__ uint32_t smem_u32(const void* p) {
    uint32_t a;
    asm("{ .reg .u64 t; cvta.to.shared.u64 t, %1; cvt.u32.u64 %0, t; }"
        : "=r"(a) : "l"(p));
    return a;
}

__global__ void lstm_init_kernel() {
    if (threadIdx.x == 0) g_cnt = 0u;
}

__global__ void __launch_bounds__(TPB) lstm_kernel(
    const float* __restrict__ x,      // [1024]
    const float* __restrict__ W_ih,   // [4096,1024] row-major
    const float* __restrict__ W_hh,   // [4096,1024] row-major
    const float* __restrict__ b_ih,   // [4096]
    const float* __restrict__ b_hh,   // [4096]
    float* __restrict__ out,          // [N,1024]
    int N)
{
    __shared__ float    sh_h[HDIM];        // warp w owns [128w,128w+128): private
    __shared__ float    sh_part[2][TPB];   // parity-double-buffered partials
    __shared__ unsigned sh_step;           // monotonic step relay

    const int tid = threadIdx.x;
    const int w   = tid >> 5;
    const int l   = tid & 31;
    const int cta = blockIdx.x;
    const int gt  = l >> 3;                // gate 0..3 (i,f,g,o)
    const int jj  = l & 7;                 // local h index 0..7
    const int rowG = gt * HDIM + cta * 8 + jj;
    const uint32_t stepAddr = smem_u32(&sh_step);

    if (tid == 0) sh_step = 0u;

    // ---- stage x into shared (reuse sh_h) ----
    ((float4*)sh_h)[tid] = ((const float4*)x)[tid];
    __syncthreads();

    // ---- prologue: x_gates = x @ W_ih^T + b_ih + b_hh for this CTA's rows ----
    // warp 0 keeps its lane's gate value in xg (all 32 lanes).
    float xg = 0.f;
    {
        const ull* wp = (const ull*)W_ih + (size_t)rowG * (HDIM / 2) + w * WPT;
        const ull* hp = (const ull*)sh_h + w * WPT;
        ull a0 = 0, a1 = 0, a2 = 0, a3 = 0;
        #pragma unroll
        for (int i = 0; i < WPT; i += 4) {
            a0 = ffma2(wp[i + 0], hp[i + 0], a0);
            a1 = ffma2(wp[i + 1], hp[i + 1], a1);
            a2 = ffma2(wp[i + 2], hp[i + 2], a2);
            a3 = ffma2(wp[i + 3], hp[i + 3], a3);
        }
        a0 = fadd2(a0, a1); a2 = fadd2(a2, a3); a0 = fadd2(a0, a2);
        sh_part[0][w * 32 + l] = pairsum(a0);
        __syncthreads();
        if (w == 0) {
            float s = 0.f;
            #pragma unroll
            for (int ww = 0; ww < NWARP; ww++) s += sh_part[0][ww * 32 + l];
            xg = s + b_ih[rowG] + b_hh[rowG];
        }
        __syncthreads();
    }

    // ---- preload W_hh slice into registers ----
    ull wreg[WPT];
    {
        const ull* wp = (const ull*)W_hh + (size_t)rowG * (HDIM / 2) + w * WPT;
        #pragma unroll
        for (int i = 0; i < WPT; i++) wreg[i] = wp[i];
    }

    // ---- recurrence: ONE __syncthreads per step ----
    float c = 0.f;
    unsigned target = 0u;                  // = 128*t

    for (int t = 0; t < N; ++t) {
        float dot = 0.f;
        if (t > 0) {
            const int p = (t - 1) & 1;
            const unsigned tt = (unsigned)t;

            if (w == 0) {
                if (l == 0) {
                    // single poller per CTA on the aggregate counter
                    while ((int)(ld_acq_gpu(&g_cnt) - target) < 0) { }
                    asm volatile("st.release.cta.shared.u32 [%0], %1;"
                                 :: "r"(stepAddr), "r"(tt) : "memory");
                }
                __syncwarp();
            } else {
                // local smem spin: zero L2 traffic
                unsigned v;
                do {
                    asm volatile("ld.acquire.cta.shared.u32 %0, [%1];"
                                 : "=r"(v) : "r"(stepAddr) : "memory");
                } while ((int)(v - tt) < 0);
            }

            // stage this warp's k-slice into its private smem region
            float4 hv = __ldcg((const float4*)(g_hbuf[p] + w * 128) + l);
            *((float4*)(sh_h + w * 128) + l) = hv;
            __syncwarp();

            const ull* hp = (const ull*)(sh_h + w * 128);
            ull c0 = 0, c1 = 0, c2 = 0, c3 = 0;
            #pragma unroll
            for (int i = 0; i < WPT; i += 4) {
                c0 = ffma2(wreg[i + 0], hp[i + 0], c0);
                c1 = ffma2(wreg[i + 1], hp[i + 1], c1);
                c2 = ffma2(wreg[i + 2], hp[i + 2], c2);
                c3 = ffma2(wreg[i + 3], hp[i + 3], c3);
            }
            c0 = fadd2(c0, c1); c2 = fadd2(c2, c3); c0 = fadd2(c0, c2);
            dot = pairsum(c0);
        }
        sh_part[t & 1][w * 32 + l] = dot;
        __syncthreads();

        if (w == 0) {
            float s = 0.f;
            #pragma unroll
            for (int ww = 0; ww < NWARP; ww++) s += sh_part[t & 1][ww * 32 + l];
            // activation on ALL 32 lanes (parallel MUFU), then gather
            float val = xg + s;
            float act = (gt == 2) ? tanhf(val) : sigf(val);
            float a_f = __shfl_sync(0xffffffffu, act, l + 8);
            float a_g = __shfl_sync(0xffffffffu, act, l + 16);
            float a_o = __shfl_sync(0xffffffffu, act, l + 24);
            float hn = 0.f;
            if (l < 8) {
                c  = a_f * c + act * a_g;       // act=i, a_f=f, a_g=g
                hn = a_o * tanhf(c);
                __stcg(&g_hbuf[t & 1][cta * 8 + l], hn);
            }
            __syncwarp();
            if (l == 0) {
                __threadfence();
                asm volatile("red.global.gpu.add.u32 [%0], %1;"
                             :: "l"(&g_cnt), "r"(1u) : "memory");
            }
            // out store AFTER release: fence never drains the DRAM write
            if (l < 8)
                __stcs(out + (size_t)t * HDIM + cta * 8 + l, hn);
        }
        target += NCTA;
        // no trailing barrier: sh_part for step t+1 has opposite parity; the
        // global counter requires ALL CTAs, bounding cross-CTA skew to 1 step.
    }
}

extern "C" void kernel_launch(void* const* d_in, const int* in_sizes, int n_in,
                              void* d_out, int out_size) {
    const float* x    = (const float*)d_in[0];
    const float* W_ih = (const float*)d_in[1];
    const float* W_hh = (const float*)d_in[2];
    const float* b_ih = (const float*)d_in[3];
    const float* b_hh = (const float*)d_in[4];
    float* out = (float*)d_out;
    const int N = out_size / HDIM;

    lstm_init_kernel<<<1, 32>>>();
    lstm_kernel<<<NCTA, TPB>>>(x, W_ih, W_hh, b_ih, b_hh, out, N);
}